// round 1
// baseline (speedup 1.0000x reference)
#include <cuda_runtime.h>
#include <math.h>

#define NB 8192
#define ND 512
#define SORT_THREADS 1024
#define NREF 8

// Scratch (no allocation allowed in kernel_launch)
__device__ int   g_nidx[NB * NREF];
__device__ float g_nw[NB * NREF];
__device__ float g_sim[NB];

// Monotone map float -> uint32 preserving order (handles negatives for safety)
__device__ __forceinline__ unsigned fkey(float f) {
    unsigned u = __float_as_uint(f);
    return (u & 0x80000000u) ? ~u : (u | 0x80000000u);
}
__device__ __forceinline__ float fkey_inv(unsigned k) {
    unsigned u = (k & 0x80000000u) ? (k & 0x7FFFFFFFu) : ~k;
    return __uint_as_float(u);
}

// ---------------------------------------------------------------------------
// Kernel 1: single-block bitonic sort of (label,index) keys, then per-point
// two-pointer neighbor selection (8 nearest incl. self) + Gaussian weights.
// ---------------------------------------------------------------------------
__global__ void k_sort_nbr(const float* __restrict__ Label) {
    extern __shared__ unsigned long long key[];  // NB * 8 bytes = 64KB
    const int tid = threadIdx.x;

    for (int i = tid; i < NB; i += SORT_THREADS) {
        key[i] = ((unsigned long long)fkey(Label[i]) << 32) | (unsigned)i;
    }

    // Bitonic sort, ascending
    for (int k = 2; k <= NB; k <<= 1) {
        for (int j = k >> 1; j > 0; j >>= 1) {
            __syncthreads();
            for (int i = tid; i < NB; i += SORT_THREADS) {
                int ixj = i ^ j;
                if (ixj > i) {
                    unsigned long long a = key[i];
                    unsigned long long b = key[ixj];
                    bool up = ((i & k) == 0);
                    if ((a > b) == up) { key[i] = b; key[ixj] = a; }
                }
            }
        }
    }
    __syncthreads();

    // Neighbor selection: the 8 nearest labels (incl. self) lie in the
    // +-7 window around each sorted position. Two-pointer expansion,
    // tie-break on smaller original index (matches jax top_k stability).
    for (int p = tid; p < NB; p += SORT_THREADS) {
        unsigned long long kp = key[p];
        float Lp = fkey_inv((unsigned)(kp >> 32));
        int   orig = (int)(kp & 0xFFFFFFFFu);

        int   sel[NREF];
        float df[NREF];
        sel[0] = orig; df[0] = 0.0f;

        int l = p - 1, r = p + 1;
        #pragma unroll
        for (int m = 1; m < NREF; m++) {
            float dl = 1e30f, dr = 1e30f;
            int ol = 0x7FFFFFFF, orr = 0x7FFFFFFF;
            if (l >= 0) {
                unsigned long long kl = key[l];
                dl = fabsf(fkey_inv((unsigned)(kl >> 32)) - Lp);
                ol = (int)(kl & 0xFFFFFFFFu);
            }
            if (r < NB) {
                unsigned long long kr = key[r];
                dr = fabsf(fkey_inv((unsigned)(kr >> 32)) - Lp);
                orr = (int)(kr & 0xFFFFFFFFu);
            }
            bool takeL = (dl < dr) || ((dl == dr) && (ol < orr));
            if (takeL) { sel[m] = ol;  df[m] = dl; l--; }
            else       { sel[m] = orr; df[m] = dr; r++; }
        }

        float w[NREF];
        float ws = 0.0f;
        #pragma unroll
        for (int m = 0; m < NREF; m++) {
            w[m] = expf(-df[m] * df[m] * (1.0f / 50.0f));  // 2*STD^2 = 50
            ws += w[m];
        }
        float inv = 1.0f / ws;
        #pragma unroll
        for (int m = 0; m < NREF; m++) {
            g_nidx[orig * NREF + m] = sel[m];
            g_nw[orig * NREF + m]   = w[m] * inv;
        }
    }
}

// ---------------------------------------------------------------------------
// Kernel 2: per-row weighted gather + cosine similarity. One block per row,
// 128 threads, float4 per thread (128*4 = 512 cols).
// ---------------------------------------------------------------------------
__global__ void __launch_bounds__(128) k_compute(const float* __restrict__ S) {
    const int i = blockIdx.x;
    const int t = threadIdx.x;

    __shared__ float w8[NREF];
    __shared__ int   i8[NREF];
    __shared__ float red[3][4];

    if (t < NREF) {
        w8[t] = g_nw[i * NREF + t];
        i8[t] = g_nidx[i * NREF + t];
    }
    __syncthreads();

    const float4* base = reinterpret_cast<const float4*>(S);
    // Row i has 128 float4s
    float4 self = base[i * (ND / 4) + t];
    float4 acc = make_float4(0.f, 0.f, 0.f, 0.f);

    #pragma unroll
    for (int m = 0; m < NREF; m++) {
        float  wm = w8[m];
        float4 v  = base[i8[m] * (ND / 4) + t];
        acc.x += wm * v.x; acc.y += wm * v.y;
        acc.z += wm * v.z; acc.w += wm * v.w;
    }

    float dot = self.x * acc.x + self.y * acc.y + self.z * acc.z + self.w * acc.w;
    float n1  = self.x * self.x + self.y * self.y + self.z * self.z + self.w * self.w;
    float n2  = acc.x * acc.x + acc.y * acc.y + acc.z * acc.z + acc.w * acc.w;

    // warp reduce (4 warps of 32)
    #pragma unroll
    for (int o = 16; o > 0; o >>= 1) {
        dot += __shfl_down_sync(0xFFFFFFFFu, dot, o);
        n1  += __shfl_down_sync(0xFFFFFFFFu, n1,  o);
        n2  += __shfl_down_sync(0xFFFFFFFFu, n2,  o);
    }
    int warp = t >> 5;
    if ((t & 31) == 0) { red[0][warp] = dot; red[1][warp] = n1; red[2][warp] = n2; }
    __syncthreads();
    if (t == 0) {
        float d = red[0][0] + red[0][1] + red[0][2] + red[0][3];
        float a = red[1][0] + red[1][1] + red[1][2] + red[1][3];
        float b = red[2][0] + red[2][1] + red[2][2] + red[2][3];
        g_sim[i] = d / ((1e-10f + sqrtf(a)) * (1e-10f + sqrtf(b)));
    }
}

// ---------------------------------------------------------------------------
// Kernel 3: deterministic tree reduction of sims -> scalar output
// ---------------------------------------------------------------------------
__global__ void k_reduce(float* __restrict__ out) {
    __shared__ float sm[32];
    const int t = threadIdx.x;  // 1024 threads
    float s = 0.0f;
    for (int i = t; i < NB; i += 1024) s += g_sim[i];
    #pragma unroll
    for (int o = 16; o > 0; o >>= 1) s += __shfl_down_sync(0xFFFFFFFFu, s, o);
    if ((t & 31) == 0) sm[t >> 5] = s;
    __syncthreads();
    if (t < 32) {
        float v = sm[t];
        #pragma unroll
        for (int o = 16; o > 0; o >>= 1) v += __shfl_down_sync(0xFFFFFFFFu, v, o);
        if (t == 0) out[0] = 1.0f - v * (1.0f / (float)NB);
    }
}

extern "C" void kernel_launch(void* const* d_in, const int* in_sizes, int n_in,
                              void* d_out, int out_size) {
    // Identify inputs by size (Struct = B*D, Label = B)
    const float* S;
    const float* L;
    if (in_sizes[0] > in_sizes[1]) { S = (const float*)d_in[0]; L = (const float*)d_in[1]; }
    else                           { S = (const float*)d_in[1]; L = (const float*)d_in[0]; }
    float* out = (float*)d_out;

    cudaFuncSetAttribute(k_sort_nbr, cudaFuncAttributeMaxDynamicSharedMemorySize,
                         NB * (int)sizeof(unsigned long long));

    k_sort_nbr<<<1, SORT_THREADS, NB * sizeof(unsigned long long)>>>(L);
    k_compute<<<NB, 128>>>(S);
    k_reduce<<<1, 1024>>>(out);
}

// round 3
// speedup vs baseline: 4.3410x; 4.3410x over previous
#include <cuda_runtime.h>
#include <math.h>

#define NB 8192
#define ND 512
#define NBUCK 8192
#define NREF 8

// Scratch (device globals — no allocation allowed)
__device__ int   g_hist[NBUCK];
__device__ int   g_start[NBUCK + 1];
__device__ int   g_cursor[NBUCK];
__device__ unsigned long long g_sorted[NB];
__device__ int   g_nidx[NB * NREF];
__device__ float g_nw[NB * NREF];
__device__ float g_sim[NB];

// Monotone map float -> uint32 preserving order
__device__ __forceinline__ unsigned fkey(float f) {
    unsigned u = __float_as_uint(f);
    return (u & 0x80000000u) ? ~u : (u | 0x80000000u);
}
__device__ __forceinline__ float fkey_inv(unsigned k) {
    unsigned u = (k & 0x80000000u) ? (k & 0x7FFFFFFFu) : ~k;
    return __uint_as_float(u);
}
__device__ __forceinline__ int bucket_of(float L) {
    int b = (int)floorf(L * (float)NBUCK);
    return b < 0 ? 0 : (b >= NBUCK ? NBUCK - 1 : b);
}

// --------------------------------------------------------------------------
__global__ void k_zero() {
    int i = blockIdx.x * blockDim.x + threadIdx.x;
    if (i < NBUCK) g_hist[i] = 0;
}

__global__ void k_hist(const float* __restrict__ Label) {
    int i = blockIdx.x * blockDim.x + threadIdx.x;
    if (i < NB) atomicAdd(&g_hist[bucket_of(Label[i])], 1);
}

// Single-block exclusive prefix scan over NBUCK=8192 (1024 threads x 8)
__global__ void k_scan() {
    __shared__ int wsum[32];
    const int t = threadIdx.x;
    int local[8];
    int s = 0;
    #pragma unroll
    for (int j = 0; j < 8; j++) { local[j] = g_hist[t * 8 + j]; s += local[j]; }

    // inclusive warp scan of s
    int lane = t & 31, warp = t >> 5;
    int v = s;
    #pragma unroll
    for (int o = 1; o < 32; o <<= 1) {
        int n = __shfl_up_sync(0xFFFFFFFFu, v, o);
        if (lane >= o) v += n;
    }
    if (lane == 31) wsum[warp] = v;
    __syncthreads();
    if (warp == 0) {
        int wv = wsum[lane];
        #pragma unroll
        for (int o = 1; o < 32; o <<= 1) {
            int n = __shfl_up_sync(0xFFFFFFFFu, wv, o);
            if (lane >= o) wv += n;
        }
        wsum[lane] = wv;
    }
    __syncthreads();
    int excl = v - s + (warp > 0 ? wsum[warp - 1] : 0);  // exclusive prefix of thread-sum

    int base = excl;
    #pragma unroll
    for (int j = 0; j < 8; j++) {
        g_start[t * 8 + j]  = base;
        g_cursor[t * 8 + j] = base;
        base += local[j];
    }
    if (t == 0) g_start[NBUCK] = NB;
}

__global__ void k_scatter(const float* __restrict__ Label) {
    int i = blockIdx.x * blockDim.x + threadIdx.x;
    if (i < NB) {
        float L = Label[i];
        int b = bucket_of(L);
        int pos = atomicAdd(&g_cursor[b], 1);
        g_sorted[pos] = ((unsigned long long)fkey(L) << 32) | (unsigned)i;
    }
}

// Deterministic within-bucket sort (full 64-bit key -> unique, stable result)
__global__ void k_bsort() {
    int b = blockIdx.x * blockDim.x + threadIdx.x;
    if (b >= NBUCK) return;
    int s = g_start[b], e = g_start[b + 1];
    for (int i = s + 1; i < e; i++) {
        unsigned long long k = g_sorted[i];
        int j = i - 1;
        while (j >= s && g_sorted[j] > k) { g_sorted[j + 1] = g_sorted[j]; j--; }
        g_sorted[j + 1] = k;
    }
}

// --------------------------------------------------------------------------
// Two-pointer neighbor selection over sorted labels + Gaussian weights.
// --------------------------------------------------------------------------
__global__ void k_nbr() {
    int p = blockIdx.x * blockDim.x + threadIdx.x;
    if (p >= NB) return;

    unsigned long long kp = g_sorted[p];
    float Lp = fkey_inv((unsigned)(kp >> 32));
    int   orig = (int)(kp & 0xFFFFFFFFu);

    int   sel[NREF];
    float df[NREF];
    sel[0] = orig; df[0] = 0.0f;

    int l = p - 1, r = p + 1;
    #pragma unroll
    for (int m = 1; m < NREF; m++) {
        float dl = 1e30f, dr = 1e30f;
        int ol = 0x7FFFFFFF, orr = 0x7FFFFFFF;
        if (l >= 0) {
            unsigned long long kl = g_sorted[l];
            dl = fabsf(fkey_inv((unsigned)(kl >> 32)) - Lp);
            ol = (int)(kl & 0xFFFFFFFFu);
        }
        if (r < NB) {
            unsigned long long kr = g_sorted[r];
            dr = fabsf(fkey_inv((unsigned)(kr >> 32)) - Lp);
            orr = (int)(kr & 0xFFFFFFFFu);
        }
        bool takeL = (dl < dr) || ((dl == dr) && (ol < orr));
        if (takeL) { sel[m] = ol;  df[m] = dl; l--; }
        else       { sel[m] = orr; df[m] = dr; r++; }
    }

    float w[NREF];
    float ws = 0.0f;
    #pragma unroll
    for (int m = 0; m < NREF; m++) {
        w[m] = __expf(-df[m] * df[m] * (1.0f / 50.0f));  // 2*STD^2 = 50
        ws += w[m];
    }
    float inv = 1.0f / ws;
    #pragma unroll
    for (int m = 0; m < NREF; m++) {
        g_nidx[orig * NREF + m] = sel[m];
        g_nw[orig * NREF + m]   = w[m] * inv;
    }
}

// --------------------------------------------------------------------------
// Per-row weighted gather + cosine similarity. One block per row, 128 thr.
// --------------------------------------------------------------------------
__global__ void __launch_bounds__(128) k_compute(const float* __restrict__ S) {
    const int i = blockIdx.x;
    const int t = threadIdx.x;

    __shared__ float w8[NREF];
    __shared__ int   i8[NREF];
    __shared__ float red[3][4];

    if (t < NREF) {
        w8[t] = g_nw[i * NREF + t];
        i8[t] = g_nidx[i * NREF + t];
    }
    __syncthreads();

    const float4* base = reinterpret_cast<const float4*>(S);
    float4 self = base[i * (ND / 4) + t];
    float4 acc = make_float4(0.f, 0.f, 0.f, 0.f);

    #pragma unroll
    for (int m = 0; m < NREF; m++) {
        float  wm = w8[m];
        float4 v  = base[i8[m] * (ND / 4) + t];
        acc.x += wm * v.x; acc.y += wm * v.y;
        acc.z += wm * v.z; acc.w += wm * v.w;
    }

    float dot = self.x * acc.x + self.y * acc.y + self.z * acc.z + self.w * acc.w;
    float n1  = self.x * self.x + self.y * self.y + self.z * self.z + self.w * self.w;
    float n2  = acc.x * acc.x + acc.y * acc.y + acc.z * acc.z + acc.w * acc.w;

    #pragma unroll
    for (int o = 16; o > 0; o >>= 1) {
        dot += __shfl_down_sync(0xFFFFFFFFu, dot, o);
        n1  += __shfl_down_sync(0xFFFFFFFFu, n1,  o);
        n2  += __shfl_down_sync(0xFFFFFFFFu, n2,  o);
    }
    int warp = t >> 5;
    if ((t & 31) == 0) { red[0][warp] = dot; red[1][warp] = n1; red[2][warp] = n2; }
    __syncthreads();
    if (t == 0) {
        float d = red[0][0] + red[0][1] + red[0][2] + red[0][3];
        float a = red[1][0] + red[1][1] + red[1][2] + red[1][3];
        float b = red[2][0] + red[2][1] + red[2][2] + red[2][3];
        g_sim[i] = d / ((1e-10f + sqrtf(a)) * (1e-10f + sqrtf(b)));
    }
}

// --------------------------------------------------------------------------
__global__ void k_reduce(float* __restrict__ out) {
    __shared__ float sm[32];
    const int t = threadIdx.x;  // 1024 threads
    float s = 0.0f;
    for (int i = t; i < NB; i += 1024) s += g_sim[i];
    #pragma unroll
    for (int o = 16; o > 0; o >>= 1) s += __shfl_down_sync(0xFFFFFFFFu, s, o);
    if ((t & 31) == 0) sm[t >> 5] = s;
    __syncthreads();
    if (t < 32) {
        float v = sm[t];
        #pragma unroll
        for (int o = 16; o > 0; o >>= 1) v += __shfl_down_sync(0xFFFFFFFFu, v, o);
        if (t == 0) out[0] = 1.0f - v * (1.0f / (float)NB);
    }
}

extern "C" void kernel_launch(void* const* d_in, const int* in_sizes, int n_in,
                              void* d_out, int out_size) {
    const float* S;
    const float* L;
    if (in_sizes[0] > in_sizes[1]) { S = (const float*)d_in[0]; L = (const float*)d_in[1]; }
    else                           { S = (const float*)d_in[1]; L = (const float*)d_in[0]; }
    float* out = (float*)d_out;

    k_zero   <<<NBUCK / 1024, 1024>>>();
    k_hist   <<<NB / 1024, 1024>>>(L);
    k_scan   <<<1, 1024>>>();
    k_scatter<<<NB / 1024, 1024>>>(L);
    k_bsort  <<<NBUCK / 1024, 1024>>>();
    k_nbr    <<<NB / 256, 256>>>();
    k_compute<<<NB, 128>>>(S);
    k_reduce <<<1, 1024>>>(out);
}